// round 6
// baseline (speedup 1.0000x reference)
#include <cuda_runtime.h>
#include <cuda_bf16.h>
#include <cstdint>
#include <math.h>

#define NROWS 8192
#define DIM   128
#define HID1  512
#define HID2  256
#define NUSERS 512

// ============ scratch: A/W stored as [hi slab | lo slab], width = 2*K ============
__device__ __align__(256) __nv_bfloat16 g_a0[NROWS * DIM * 2];    // [8192, 256]
__device__ __align__(256) __nv_bfloat16 g_a1[NROWS * HID1 * 2];   // [8192, 1024]
__device__ __align__(256) __nv_bfloat16 g_a2[NROWS * HID2 * 2];   // [8192, 512]
__device__ __align__(256) __nv_bfloat16 g_w1[HID1 * DIM * 2];     // [512, 256]   (W1^T)
__device__ __align__(256) __nv_bfloat16 g_w2[HID2 * HID1 * 2];    // [256, 1024]  (W2^T)
__device__ __align__(256) __nv_bfloat16 g_w3[DIM * HID2 * 2];     // [128, 512]   (W3^T)
__device__ int g_cnt[NUSERS], g_off[NUSERS];
__device__ int g_idx[NROWS], g_tsb[NROWS];
__device__ int g_rowcnt[NROWS];
__device__ int g_is64, g_clickbyte;

// ============================ helpers ============================
__device__ __forceinline__ uint32_t smem_to_u32(const void* p) {
    uint32_t a;
    asm("{ .reg .u64 t; cvta.to.shared.u64 t, %1; cvt.u32.u64 %0, t; }" : "=r"(a) : "l"(p));
    return a;
}
__device__ __forceinline__ void cp_async16(uint32_t smem, const void* gmem) {
    asm volatile("cp.async.cg.shared.global [%0], [%1], 16;" :: "r"(smem), "l"(gmem));
}
#define CP_COMMIT() asm volatile("cp.async.commit_group;" ::: "memory")
#define CP_WAIT(n)  asm volatile("cp.async.wait_group %0;" :: "n"(n) : "memory")

__device__ __forceinline__ void mma_bf16(float d[4], const uint32_t a[4], const uint32_t b[2]) {
    asm volatile(
        "mma.sync.aligned.m16n8k16.row.col.f32.bf16.bf16.f32 "
        "{%0,%1,%2,%3}, {%4,%5,%6,%7}, {%8,%9}, {%0,%1,%2,%3};"
        : "+f"(d[0]), "+f"(d[1]), "+f"(d[2]), "+f"(d[3])
        : "r"(a[0]), "r"(a[1]), "r"(a[2]), "r"(a[3]), "r"(b[0]), "r"(b[1]));
}
__device__ __forceinline__ void hilo_split(float v, __nv_bfloat16& hi, __nv_bfloat16& lo) {
    hi = __float2bfloat16(v);
    lo = __float2bfloat16(v - __bfloat162float(hi));
}
__device__ __forceinline__ int ld_user(const void* p, int j, int is64) {
    return is64 ? (int)((const long long*)p)[j] : ((const int*)p)[j];
}
__device__ __forceinline__ long long ld_ts(const void* p, int j, int is64) {
    return is64 ? ((const long long*)p)[j] : (long long)((const int*)p)[j];
}
__device__ __forceinline__ int ld_click(const void* p, int j, int cb) {
    return cb ? (((const unsigned char*)p)[j] != 0) : (((const int*)p)[j] != 0);
}

// ============ fused prep: detect + count + scan + scatter + sort (1 block) ============
__global__ void k_prep(const void* __restrict__ user, const void* __restrict__ ts,
                       const void* __restrict__ click) {
    __shared__ int cnt[NUSERS], off[NUSERS], fill[NUSERS];
    __shared__ int s_ts_or, s_click_big;
    int t = threadIdx.x;
    if (t == 0) { s_ts_or = 0; s_click_big = 0; }
    __syncthreads();
    {
        const unsigned int* tsw = (const unsigned int*)ts;
        unsigned int acc = 0;
        for (int i = t; i < 2048; i += NUSERS) acc |= tsw[2 * i + 1];
        if (acc) atomicOr(&s_ts_or, 1);
        const unsigned int* cw = (const unsigned int*)click;
        int big = 0;
        for (int i = t; i < 2048; i += NUSERS) if (cw[i] > 1u) big = 1;
        if (big) atomicOr(&s_click_big, 1);
    }
    cnt[t] = 0; fill[t] = 0;
    __syncthreads();
    int is64 = (s_ts_or == 0) ? 1 : 0;
    int cb = s_click_big ? 1 : 0;
    for (int j = t; j < NROWS; j += NUSERS)
        if (ld_click(click, j, cb)) atomicAdd(&cnt[ld_user(user, j, is64)], 1);
    __syncthreads();
    {
        int v = cnt[t];
        off[t] = v;
        __syncthreads();
        for (int o = 1; o < NUSERS; o <<= 1) {
            int x = (t >= o) ? off[t - o] : 0;
            __syncthreads();
            off[t] += x;
            __syncthreads();
        }
        off[t] -= v;
    }
    __syncthreads();
    for (int j = t; j < NROWS; j += NUSERS)
        if (ld_click(click, j, cb)) {
            int u = ld_user(user, j, is64);
            int pos = off[u] + atomicAdd(&fill[u], 1);
            g_idx[pos] = j;
            g_tsb[pos] = (int)ld_ts(ts, j, is64);
        }
    __syncthreads();
    {
        int b = off[t], n = cnt[t];
        for (int i = 1; i < n; i++) {
            int kj = g_idx[b + i], kt = g_tsb[b + i];
            int p = i - 1;
            while (p >= 0 && g_idx[b + p] > kj) {
                g_idx[b + p + 1] = g_idx[b + p];
                g_tsb[b + p + 1] = g_tsb[b + p];
                p--;
            }
            g_idx[b + p + 1] = kj;
            g_tsb[b + p + 1] = kt;
        }
    }
    g_off[t] = off[t];
    g_cnt[t] = cnt[t];
    if (t == 0) { g_is64 = is64; g_clickbyte = cb; }
}

// ============ history: mean of clicked-earlier ad rows -> hi/lo slabs ============
__global__ void k_hist(const float* __restrict__ ad, const void* __restrict__ user,
                       const void* __restrict__ ts) {
    int i = blockIdx.x;
    int t = threadIdx.x;           // 0..127 dim
    int is64 = g_is64;
    int u = ld_user(user, i, is64);
    long long ti = ld_ts(ts, i, is64);
    int b = g_off[u], n = g_cnt[u];
    float acc = 0.f;
    int c = 0;
    for (int k = 0; k < n; k++) {
        if ((long long)g_tsb[b + k] < ti) {
            acc += ad[g_idx[b + k] * DIM + t];
            c++;
        }
    }
    float v = c ? acc / (float)c : 0.f;
    __nv_bfloat16 hi, lo;
    hilo_split(v, hi, lo);
    g_a0[i * (2 * DIM) + t] = hi;
    g_a0[i * (2 * DIM) + DIM + t] = lo;
    if (t == 0) g_rowcnt[i] = c;
}

// ============ weight transpose + hi/lo slab split ============
__global__ void k_wsplit(const float* __restrict__ W1, const float* __restrict__ W2,
                         const float* __restrict__ W3) {
    int stride = gridDim.x * blockDim.x;
    int tid = blockIdx.x * blockDim.x + threadIdx.x;
    for (int i = tid; i < DIM * HID1; i += stride) {       // W1 [128,512] -> g_w1 [512, 2*128]
        int k = i >> 9, n = i & 511;
        __nv_bfloat16 hi, lo;
        hilo_split(W1[i], hi, lo);
        g_w1[n * (2 * DIM) + k] = hi;
        g_w1[n * (2 * DIM) + DIM + k] = lo;
    }
    for (int i = tid; i < HID1 * HID2; i += stride) {      // W2 [512,256] -> g_w2 [256, 2*512]
        int k = i >> 8, n = i & 255;
        __nv_bfloat16 hi, lo;
        hilo_split(W2[i], hi, lo);
        g_w2[n * (2 * HID1) + k] = hi;
        g_w2[n * (2 * HID1) + HID1 + k] = lo;
    }
    for (int i = tid; i < HID2 * DIM; i += stride) {       // W3 [256,128] -> g_w3 [128, 2*256]
        int k = i >> 7, n = i & 127;
        __nv_bfloat16 hi, lo;
        hilo_split(W3[i], hi, lo);
        g_w3[n * (2 * HID2) + k] = hi;
        g_w3[n * (2 * HID2) + HID2 + k] = lo;
    }
}

// ============ mma.sync GEMM: 128x128 CTA tile, virtual K' = 3*KLOG via 3 segments ============
// A: [M, 2*KLOG] = [Ahi | Alo], B: [Nfull, 2*KLOG] = [Bhi | Blo] (= W^T split).
// Segment s of K': s=0 -> Ahi*Bhi, s=1 -> Ahi*Blo, s=2 -> Alo*Bhi
//   => D = AhiBhi + AhiBlo + AloBhi  (3-term compensated bf16, ~1e-5 rel err).
// K-chunk 64, 2-stage cp.async pipeline, SMEM rows padded to 144B (conflict-free).
// EPI 0: bias+SiLU -> hi/lo slab bf16 out (width 2*Nfull).
// EPI 1: bias -> L2 norm -> empty mask -> fp32 out (Nfull == 128).
#define ROWB 144
#define MATB (128 * ROWB)      // 18432
#define STGB (2 * MATB)        // 36864
static constexpr int GEMM_SMEM = 2 * STGB;   // 73728 -> 2 CTAs/SM

template<int KLOG, int EPI>
__global__ __launch_bounds__(256, 2)
void gemm_mma(const __nv_bfloat16* __restrict__ A, const __nv_bfloat16* __restrict__ B,
              const float* __restrict__ bias, int Nfull,
              __nv_bfloat16* __restrict__ outAB,
              const int* __restrict__ rowcnt, float* __restrict__ outF) {
    constexpr int KT = 2 * KLOG;         // physical row width
    constexpr int CPS = KLOG / 64;       // chunks per segment
    constexpr int NCH = 3 * CPS;         // total K' chunks
    extern __shared__ char sm[];
    const int tid = threadIdx.x, wid = tid >> 5, lane = tid & 31;
    const int wm = wid & 1, wn = wid >> 1;            // 2 (m) x 4 (n) warps
    const int lq = lane & 3, lr = lane >> 2;
    const int bm = blockIdx.y * 128, bn = blockIdx.x * 128;
    const uint32_t smem0 = smem_to_u32(sm);

    float d[4][4][4];
    #pragma unroll
    for (int mt = 0; mt < 4; mt++)
        #pragma unroll
        for (int nt = 0; nt < 4; nt++)
            #pragma unroll
            for (int q = 0; q < 4; q++) d[mt][nt][q] = 0.f;

    auto load_stage = [&](int s, int ch) {
        int seg = ch / CPS;
        int ks = (ch - seg * CPS) * 64;
        int aOff = (seg == 2) ? (KLOG + ks) : ks;     // seg 0,1: Ahi; seg 2: Alo
        int bOff = (seg == 1) ? (KLOG + ks) : ks;     // seg 0,2: Bhi; seg 1: Blo
        uint32_t sb = smem0 + (uint32_t)s * STGB;
        #pragma unroll
        for (int i = tid; i < 1024; i += 256) {
            int r = i >> 3, c = i & 7;
            uint32_t so = (uint32_t)(r * ROWB + c * 16);
            cp_async16(sb + so,        A + (size_t)(bm + r) * KT + aOff + c * 8);
            cp_async16(sb + MATB + so, B + (size_t)(bn + r) * KT + bOff + c * 8);
        }
    };

    load_stage(0, 0);
    CP_COMMIT();
    for (int ch = 0; ch < NCH; ch++) {
        if (ch + 1 < NCH) { load_stage((ch + 1) & 1, ch + 1); CP_COMMIT(); CP_WAIT(1); }
        else              { CP_WAIT(0); }
        __syncthreads();
        const char* pA = sm + (size_t)(ch & 1) * STGB;
        const char* pB = pA + MATB;
        #pragma unroll
        for (int ks = 0; ks < 4; ks++) {
            uint32_t Af[4][4], Bf[4][2];
            #pragma unroll
            for (int mt = 0; mt < 4; mt++) {
                int r0 = wm * 64 + mt * 16 + lr;
                const uint32_t* w0 = (const uint32_t*)(pA + r0 * ROWB);
                const uint32_t* w1 = (const uint32_t*)(pA + (r0 + 8) * ROWB);
                Af[mt][0] = w0[ks * 8 + lq];
                Af[mt][1] = w1[ks * 8 + lq];
                Af[mt][2] = w0[ks * 8 + lq + 4];
                Af[mt][3] = w1[ks * 8 + lq + 4];
            }
            #pragma unroll
            for (int nt = 0; nt < 4; nt++) {
                int n0 = wn * 32 + nt * 8 + lr;
                const uint32_t* wb = (const uint32_t*)(pB + n0 * ROWB);
                Bf[nt][0] = wb[ks * 8 + lq];
                Bf[nt][1] = wb[ks * 8 + lq + 4];
            }
            #pragma unroll
            for (int mt = 0; mt < 4; mt++)
                #pragma unroll
                for (int nt = 0; nt < 4; nt++) mma_bf16(d[mt][nt], Af[mt], Bf[nt]);
        }
        __syncthreads();
    }

    if (EPI == 0) {
        // bias + SiLU -> hi/lo slab store (out width = 2*Nfull)
        #pragma unroll
        for (int mt = 0; mt < 4; mt++) {
            int row0 = bm + wm * 64 + mt * 16 + lr;
            #pragma unroll
            for (int nt = 0; nt < 4; nt++) {
                int col = bn + wn * 32 + nt * 8 + lq * 2;
                float2 bb = *(const float2*)&bias[col];
                #pragma unroll
                for (int h = 0; h < 2; h++) {
                    int row = row0 + h * 8;
                    float x0 = d[mt][nt][2 * h + 0] + bb.x;
                    float x1 = d[mt][nt][2 * h + 1] + bb.y;
                    float s0 = x0 / (1.f + __expf(-x0));
                    float s1 = x1 / (1.f + __expf(-x1));
                    __nv_bfloat16 h0, l0, h1, l1;
                    hilo_split(s0, h0, l0);
                    hilo_split(s1, h1, l1);
                    __nv_bfloat162 ph = __halves2bfloat162(h0, h1);
                    __nv_bfloat162 pl = __halves2bfloat162(l0, l1);
                    size_t rbase = (size_t)row * (2 * Nfull);
                    ((uint32_t*)outAB)[(rbase + col) >> 1]         = *(uint32_t*)&ph;
                    ((uint32_t*)outAB)[(rbase + Nfull + col) >> 1] = *(uint32_t*)&pl;
                }
            }
        }
    } else {
        // bias + L2 norm + empty mask (Nfull == 128, bn == 0); deterministic reduce
        float* sqp = (float*)sm;   // [4 n-warps][128 rows]
        for (int i = tid; i < 512; i += 256) sqp[i] = 0.f;
        __syncthreads();
        #pragma unroll
        for (int mt = 0; mt < 4; mt++) {
            #pragma unroll
            for (int h = 0; h < 2; h++) {
                float s = 0.f;
                #pragma unroll
                for (int nt = 0; nt < 4; nt++) {
                    int col = wn * 32 + nt * 8 + lq * 2;
                    float2 bb = *(const float2*)&bias[col];
                    float e0 = d[mt][nt][2 * h + 0] + bb.x;
                    float e1 = d[mt][nt][2 * h + 1] + bb.y;
                    s += e0 * e0 + e1 * e1;
                }
                s += __shfl_xor_sync(0xffffffffu, s, 1);
                s += __shfl_xor_sync(0xffffffffu, s, 2);
                if (lq == 0) sqp[wn * 128 + wm * 64 + mt * 16 + lr + h * 8] = s;
            }
        }
        __syncthreads();
        #pragma unroll
        for (int mt = 0; mt < 4; mt++) {
            #pragma unroll
            for (int h = 0; h < 2; h++) {
                int rl = wm * 64 + mt * 16 + lr + h * 8;
                float S = sqp[rl] + sqp[128 + rl] + sqp[256 + rl] + sqp[384 + rl];
                float sc = 0.f;
                if (rowcnt[bm + rl] > 0 && S > 0.f) sc = rsqrtf(S);
                #pragma unroll
                for (int nt = 0; nt < 4; nt++) {
                    int col = wn * 32 + nt * 8 + lq * 2;
                    float2 bb = *(const float2*)&bias[col];
                    float2 v;
                    v.x = (d[mt][nt][2 * h + 0] + bb.x) * sc;
                    v.y = (d[mt][nt][2 * h + 1] + bb.y) * sc;
                    *(float2*)&outF[(size_t)(bm + rl) * 128 + col] = v;
                }
            }
        }
    }
}

// ============================ launch ============================
extern "C" void kernel_launch(void* const* d_in, const int* in_sizes, int n_in,
                              void* d_out, int out_size) {
    const float* ad    = (const float*)d_in[0];
    const void*  user  = d_in[1];
    const void*  ts    = d_in[2];
    const void*  click = d_in[3];
    const float* W1 = (const float*)d_in[4];
    const float* b1 = (const float*)d_in[5];
    const float* W2 = (const float*)d_in[6];
    const float* b2 = (const float*)d_in[7];
    const float* W3 = (const float*)d_in[8];
    const float* b3 = (const float*)d_in[9];
    float* out = (float*)d_out;

    cudaFuncSetAttribute(gemm_mma<128, 0>, cudaFuncAttributeMaxDynamicSharedMemorySize, GEMM_SMEM);
    cudaFuncSetAttribute(gemm_mma<512, 0>, cudaFuncAttributeMaxDynamicSharedMemorySize, GEMM_SMEM);
    cudaFuncSetAttribute(gemm_mma<256, 1>, cudaFuncAttributeMaxDynamicSharedMemorySize, GEMM_SMEM);

    __nv_bfloat16 *a0, *a1, *a2, *w1, *w2, *w3;
    int* rowcnt;
    cudaGetSymbolAddress((void**)&a0, g_a0);
    cudaGetSymbolAddress((void**)&a1, g_a1);
    cudaGetSymbolAddress((void**)&a2, g_a2);
    cudaGetSymbolAddress((void**)&w1, g_w1);
    cudaGetSymbolAddress((void**)&w2, g_w2);
    cudaGetSymbolAddress((void**)&w3, g_w3);
    cudaGetSymbolAddress((void**)&rowcnt, g_rowcnt);

    k_prep<<<1, NUSERS>>>(user, ts, click);
    k_wsplit<<<128, 256>>>(W1, W2, W3);
    k_hist<<<NROWS, DIM>>>(ad, user, ts);

    // L1: a0[8192, 2*128] @ w1[512, 2*128] -> silu -> a1 [8192, 2*512]
    gemm_mma<128, 0><<<dim3(HID1 / 128, NROWS / 128), 256, GEMM_SMEM>>>(
        a0, w1, b1, HID1, a1, nullptr, nullptr);
    // L2: a1 @ w2[256, 2*512] -> silu -> a2 [8192, 2*256]
    gemm_mma<512, 0><<<dim3(HID2 / 128, NROWS / 128), 256, GEMM_SMEM>>>(
        a1, w2, b2, HID2, a2, nullptr, nullptr);
    // L3: a2 @ w3[128, 2*256] -> bias -> L2norm -> mask -> out
    gemm_mma<256, 1><<<dim3(1, NROWS / 128), 256, GEMM_SMEM>>>(
        a2, w3, b3, DIM, nullptr, rowcnt, out);
}

// round 7
// speedup vs baseline: 1.0254x; 1.0254x over previous
#include <cuda_runtime.h>
#include <cuda_bf16.h>
#include <cstdint>
#include <math.h>

#define NROWS 8192
#define DIM   128
#define HID1  512
#define HID2  256
#define NUSERS 512

// ============ scratch: A/W stored as [hi slab | lo slab], width = 2*K ============
__device__ __align__(256) __nv_bfloat16 g_a0[NROWS * DIM * 2];    // [8192, 256]
__device__ __align__(256) __nv_bfloat16 g_a1[NROWS * HID1 * 2];   // [8192, 1024]
__device__ __align__(256) __nv_bfloat16 g_a2[NROWS * HID2 * 2];   // [8192, 512]
__device__ __align__(256) __nv_bfloat16 g_w1[HID1 * DIM * 2];     // [512, 256]   (W1^T)
__device__ __align__(256) __nv_bfloat16 g_w2[HID2 * HID1 * 2];    // [256, 1024]  (W2^T)
__device__ __align__(256) __nv_bfloat16 g_w3[DIM * HID2 * 2];     // [128, 512]   (W3^T)
__device__ int g_cnt[NUSERS], g_off[NUSERS];
__device__ int g_idx[NROWS], g_tsb[NROWS];
__device__ int g_rowcnt[NROWS];
__device__ int g_is64, g_clickbyte;

// ============================ helpers ============================
__device__ __forceinline__ uint32_t smem_to_u32(const void* p) {
    uint32_t a;
    asm("{ .reg .u64 t; cvta.to.shared.u64 t, %1; cvt.u32.u64 %0, t; }" : "=r"(a) : "l"(p));
    return a;
}
__device__ __forceinline__ void cp_async16(uint32_t smem, const void* gmem) {
    asm volatile("cp.async.cg.shared.global [%0], [%1], 16;" :: "r"(smem), "l"(gmem));
}
#define CP_COMMIT() asm volatile("cp.async.commit_group;" ::: "memory")
#define CP_WAIT(n)  asm volatile("cp.async.wait_group %0;" :: "n"(n) : "memory")

__device__ __forceinline__ void ldsm_x4(uint32_t r[4], uint32_t addr) {
    asm volatile("ldmatrix.sync.aligned.m8n8.x4.shared.b16 {%0,%1,%2,%3}, [%4];"
                 : "=r"(r[0]), "=r"(r[1]), "=r"(r[2]), "=r"(r[3]) : "r"(addr));
}
__device__ __forceinline__ void mma_bf16(float d[4], const uint32_t a[4], const uint32_t b[2]) {
    asm volatile(
        "mma.sync.aligned.m16n8k16.row.col.f32.bf16.bf16.f32 "
        "{%0,%1,%2,%3}, {%4,%5,%6,%7}, {%8,%9}, {%0,%1,%2,%3};"
        : "+f"(d[0]), "+f"(d[1]), "+f"(d[2]), "+f"(d[3])
        : "r"(a[0]), "r"(a[1]), "r"(a[2]), "r"(a[3]), "r"(b[0]), "r"(b[1]));
}
__device__ __forceinline__ void hilo_split(float v, __nv_bfloat16& hi, __nv_bfloat16& lo) {
    hi = __float2bfloat16(v);
    lo = __float2bfloat16(v - __bfloat162float(hi));
}
__device__ __forceinline__ int ld_user(const void* p, int j, int is64) {
    return is64 ? (int)((const long long*)p)[j] : ((const int*)p)[j];
}
__device__ __forceinline__ long long ld_ts(const void* p, int j, int is64) {
    return is64 ? ((const long long*)p)[j] : (long long)((const int*)p)[j];
}
__device__ __forceinline__ int ld_click(const void* p, int j, int cb) {
    return cb ? (((const unsigned char*)p)[j] != 0) : (((const int*)p)[j] != 0);
}

// ============ fused prep: detect + count + scan + scatter + sort (1 block) ============
__global__ void k_prep(const void* __restrict__ user, const void* __restrict__ ts,
                       const void* __restrict__ click) {
    __shared__ int cnt[NUSERS], off[NUSERS], fill[NUSERS];
    __shared__ int s_ts_or, s_click_big;
    int t = threadIdx.x;
    if (t == 0) { s_ts_or = 0; s_click_big = 0; }
    __syncthreads();
    {
        const unsigned int* tsw = (const unsigned int*)ts;
        unsigned int acc = 0;
        for (int i = t; i < 2048; i += NUSERS) acc |= tsw[2 * i + 1];
        if (acc) atomicOr(&s_ts_or, 1);
        const unsigned int* cw = (const unsigned int*)click;
        int big = 0;
        for (int i = t; i < 2048; i += NUSERS) if (cw[i] > 1u) big = 1;
        if (big) atomicOr(&s_click_big, 1);
    }
    cnt[t] = 0; fill[t] = 0;
    __syncthreads();
    int is64 = (s_ts_or == 0) ? 1 : 0;
    int cb = s_click_big ? 1 : 0;
    for (int j = t; j < NROWS; j += NUSERS)
        if (ld_click(click, j, cb)) atomicAdd(&cnt[ld_user(user, j, is64)], 1);
    __syncthreads();
    {
        int v = cnt[t];
        off[t] = v;
        __syncthreads();
        for (int o = 1; o < NUSERS; o <<= 1) {
            int x = (t >= o) ? off[t - o] : 0;
            __syncthreads();
            off[t] += x;
            __syncthreads();
        }
        off[t] -= v;
    }
    __syncthreads();
    for (int j = t; j < NROWS; j += NUSERS)
        if (ld_click(click, j, cb)) {
            int u = ld_user(user, j, is64);
            int pos = off[u] + atomicAdd(&fill[u], 1);
            g_idx[pos] = j;
            g_tsb[pos] = (int)ld_ts(ts, j, is64);
        }
    __syncthreads();
    {
        int b = off[t], n = cnt[t];
        for (int i = 1; i < n; i++) {
            int kj = g_idx[b + i], kt = g_tsb[b + i];
            int p = i - 1;
            while (p >= 0 && g_idx[b + p] > kj) {
                g_idx[b + p + 1] = g_idx[b + p];
                g_tsb[b + p + 1] = g_tsb[b + p];
                p--;
            }
            g_idx[b + p + 1] = kj;
            g_tsb[b + p + 1] = kt;
        }
    }
    g_off[t] = off[t];
    g_cnt[t] = cnt[t];
    if (t == 0) { g_is64 = is64; g_clickbyte = cb; }
}

// ============ history: mean of clicked-earlier ad rows -> hi/lo slabs ============
__global__ void k_hist(const float* __restrict__ ad, const void* __restrict__ user,
                       const void* __restrict__ ts) {
    int i = blockIdx.x;
    int t = threadIdx.x;           // 0..127 dim
    int is64 = g_is64;
    int u = ld_user(user, i, is64);
    long long ti = ld_ts(ts, i, is64);
    int b = g_off[u], n = g_cnt[u];
    float acc = 0.f;
    int c = 0;
    for (int k = 0; k < n; k++) {
        if ((long long)g_tsb[b + k] < ti) {
            acc += ad[g_idx[b + k] * DIM + t];
            c++;
        }
    }
    float v = c ? acc / (float)c : 0.f;
    __nv_bfloat16 hi, lo;
    hilo_split(v, hi, lo);
    g_a0[i * (2 * DIM) + t] = hi;
    g_a0[i * (2 * DIM) + DIM + t] = lo;
    if (t == 0) g_rowcnt[i] = c;
}

// ============ weight transpose + hi/lo slab split ============
__global__ void k_wsplit(const float* __restrict__ W1, const float* __restrict__ W2,
                         const float* __restrict__ W3) {
    int stride = gridDim.x * blockDim.x;
    int tid = blockIdx.x * blockDim.x + threadIdx.x;
    for (int i = tid; i < DIM * HID1; i += stride) {       // W1 [128,512] -> g_w1 [512, 2*128]
        int k = i >> 9, n = i & 511;
        __nv_bfloat16 hi, lo;
        hilo_split(W1[i], hi, lo);
        g_w1[n * (2 * DIM) + k] = hi;
        g_w1[n * (2 * DIM) + DIM + k] = lo;
    }
    for (int i = tid; i < HID1 * HID2; i += stride) {      // W2 [512,256] -> g_w2 [256, 2*512]
        int k = i >> 8, n = i & 255;
        __nv_bfloat16 hi, lo;
        hilo_split(W2[i], hi, lo);
        g_w2[n * (2 * HID1) + k] = hi;
        g_w2[n * (2 * HID1) + HID1 + k] = lo;
    }
    for (int i = tid; i < HID2 * DIM; i += stride) {       // W3 [256,128] -> g_w3 [128, 2*256]
        int k = i >> 7, n = i & 127;
        __nv_bfloat16 hi, lo;
        hilo_split(W3[i], hi, lo);
        g_w3[n * (2 * HID2) + k] = hi;
        g_w3[n * (2 * HID2) + HID2 + k] = lo;
    }
}

// ============ mma.sync GEMM: 128x128 CTA tile, virtual K' = 3*KLOG via 3 segments ============
// A: [M, 2*KLOG] = [Ahi | Alo], B: [Nfull, 2*KLOG] = [Bhi | Blo] (= W^T split).
// Segment s: s=0 -> Ahi*Bhi, s=1 -> Ahi*Blo, s=2 -> Alo*Bhi
//   => D = AhiBhi + AhiBlo + AloBhi  (3-term compensated bf16, ~1e-5 rel err).
// K-chunk 64, 3-stage cp.async pipeline (1 syncthreads/chunk), ldmatrix fragment loads.
// SMEM rows padded to 144B -> rows hit banks 4r..4r+3 (conflict-free LDSM phases).
// EPI 0: bias+SiLU -> hi/lo slab bf16 out (width 2*Nfull).
// EPI 1: bias -> L2 norm -> empty mask -> fp32 out (Nfull == 128).
#define ROWB 144
#define MATB (128 * ROWB)      // 18432
#define STGB (2 * MATB)        // 36864
static constexpr int GEMM_SMEM = 3 * STGB;   // 110592; 2 CTAs/SM (221KB < 228KB)

template<int KLOG, int EPI>
__global__ __launch_bounds__(256, 2)
void gemm_mma(const __nv_bfloat16* __restrict__ A, const __nv_bfloat16* __restrict__ B,
              const float* __restrict__ bias, int Nfull,
              __nv_bfloat16* __restrict__ outAB,
              const int* __restrict__ rowcnt, float* __restrict__ outF) {
    constexpr int KT = 2 * KLOG;         // physical row width
    constexpr int CPS = KLOG / 64;       // chunks per segment
    constexpr int NCH = 3 * CPS;         // total K' chunks
    extern __shared__ char sm[];
    const int tid = threadIdx.x, wid = tid >> 5, lane = tid & 31;
    const int wm = wid & 1, wn = wid >> 1;            // 2 (m) x 4 (n) warps
    const int lq = lane & 3, lr = lane >> 2;
    const int bm = blockIdx.y * 128, bn = blockIdx.x * 128;
    const uint32_t smem0 = smem_to_u32(sm);

    // ldmatrix per-thread address offsets (within a matrix), verified fragment mapping:
    // A x4: mat0 rows0-7/k0-7 -> a0, mat1 rows8-15/k0-7 -> a1, mat2 k8-15 -> a2, mat3 -> a3
    const uint32_t aOff = (uint32_t)((((lane >> 3) & 1) * 8 + (lane & 7)) * ROWB
                                     + (lane >> 4) * 16 + (wm * 64) * ROWB);
    // B x4 (2 n-tiles): mat0 n0-7/k0-7 -> b0(nt), mat1 n0-7/k8-15 -> b1(nt),
    //                   mat2 n8-15/k0-7 -> b0(nt+1), mat3 -> b1(nt+1)
    const uint32_t bOff = (uint32_t)(((((lane >> 4) & 1) * 8) + (lane & 7)) * ROWB
                                     + ((lane >> 3) & 1) * 16 + (wn * 32) * ROWB);

    float d[4][4][4];
    #pragma unroll
    for (int mt = 0; mt < 4; mt++)
        #pragma unroll
        for (int nt = 0; nt < 4; nt++)
            #pragma unroll
            for (int q = 0; q < 4; q++) d[mt][nt][q] = 0.f;

    auto load_stage = [&](int s, int ch) {
        int seg = ch / CPS;
        int ks0 = (ch - seg * CPS) * 64;
        int aO = (seg == 2) ? (KLOG + ks0) : ks0;     // seg 0,1: Ahi; seg 2: Alo
        int bO = (seg == 1) ? (KLOG + ks0) : ks0;     // seg 0,2: Bhi; seg 1: Blo
        uint32_t sb = smem0 + (uint32_t)s * STGB;
        #pragma unroll
        for (int i = tid; i < 1024; i += 256) {
            int r = i >> 3, c = i & 7;
            uint32_t so = (uint32_t)(r * ROWB + c * 16);
            cp_async16(sb + so,        A + (size_t)(bm + r) * KT + aO + c * 8);
            cp_async16(sb + MATB + so, B + (size_t)(bn + r) * KT + bO + c * 8);
        }
    };

    load_stage(0, 0);
    CP_COMMIT();
    load_stage(1, 1);
    CP_COMMIT();

    int stage = 0;
    for (int ch = 0; ch < NCH; ch++) {
        if (ch + 1 < NCH) { CP_WAIT(1); } else { CP_WAIT(0); }
        __syncthreads();   // chunk ch visible; prior chunk's readers done (buffer reuse safe)
        if (ch + 2 < NCH) {
            int ns = stage + 2; if (ns >= 3) ns -= 3;
            load_stage(ns, ch + 2);
            CP_COMMIT();
        }
        uint32_t sA = smem0 + (uint32_t)stage * STGB;
        uint32_t sB = sA + MATB;
        #pragma unroll
        for (int ks = 0; ks < 4; ks++) {
            uint32_t Af[4][4], Bf[2][4];
            #pragma unroll
            for (int mt = 0; mt < 4; mt++)
                ldsm_x4(Af[mt], sA + aOff + (uint32_t)(mt * 16 * ROWB + ks * 32));
            ldsm_x4(Bf[0], sB + bOff + (uint32_t)(ks * 32));
            ldsm_x4(Bf[1], sB + bOff + (uint32_t)(16 * ROWB + ks * 32));
            #pragma unroll
            for (int mt = 0; mt < 4; mt++)
                #pragma unroll
                for (int nt = 0; nt < 4; nt++)
                    mma_bf16(d[mt][nt], Af[mt], &Bf[nt >> 1][(nt & 1) * 2]);
        }
        stage++; if (stage >= 3) stage = 0;
    }
    __syncthreads();

    if (EPI == 0) {
        // bias + SiLU -> hi/lo slab store (out width = 2*Nfull)
        #pragma unroll
        for (int mt = 0; mt < 4; mt++) {
            int row0 = bm + wm * 64 + mt * 16 + lr;
            #pragma unroll
            for (int nt = 0; nt < 4; nt++) {
                int col = bn + wn * 32 + nt * 8 + lq * 2;
                float2 bb = *(const float2*)&bias[col];
                #pragma unroll
                for (int h = 0; h < 2; h++) {
                    int row = row0 + h * 8;
                    float x0 = d[mt][nt][2 * h + 0] + bb.x;
                    float x1 = d[mt][nt][2 * h + 1] + bb.y;
                    float s0 = x0 / (1.f + __expf(-x0));
                    float s1 = x1 / (1.f + __expf(-x1));
                    __nv_bfloat16 h0, l0, h1, l1;
                    hilo_split(s0, h0, l0);
                    hilo_split(s1, h1, l1);
                    __nv_bfloat162 ph = __halves2bfloat162(h0, h1);
                    __nv_bfloat162 pl = __halves2bfloat162(l0, l1);
                    size_t rbase = (size_t)row * (2 * Nfull);
                    ((uint32_t*)outAB)[(rbase + col) >> 1]         = *(uint32_t*)&ph;
                    ((uint32_t*)outAB)[(rbase + Nfull + col) >> 1] = *(uint32_t*)&pl;
                }
            }
        }
    } else {
        // bias + L2 norm + empty mask (Nfull == 128, bn == 0); deterministic reduce
        float* sqp = (float*)sm;   // [4 n-warps][128 rows]
        for (int i = tid; i < 512; i += 256) sqp[i] = 0.f;
        __syncthreads();
        #pragma unroll
        for (int mt = 0; mt < 4; mt++) {
            #pragma unroll
            for (int h = 0; h < 2; h++) {
                float s = 0.f;
                #pragma unroll
                for (int nt = 0; nt < 4; nt++) {
                    int col = wn * 32 + nt * 8 + lq * 2;
                    float2 bb = *(const float2*)&bias[col];
                    float e0 = d[mt][nt][2 * h + 0] + bb.x;
                    float e1 = d[mt][nt][2 * h + 1] + bb.y;
                    s += e0 * e0 + e1 * e1;
                }
                s += __shfl_xor_sync(0xffffffffu, s, 1);
                s += __shfl_xor_sync(0xffffffffu, s, 2);
                if (lq == 0) sqp[wn * 128 + wm * 64 + mt * 16 + lr + h * 8] = s;
            }
        }
        __syncthreads();
        #pragma unroll
        for (int mt = 0; mt < 4; mt++) {
            #pragma unroll
            for (int h = 0; h < 2; h++) {
                int rl = wm * 64 + mt * 16 + lr + h * 8;
                float S = sqp[rl] + sqp[128 + rl] + sqp[256 + rl] + sqp[384 + rl];
                float sc = 0.f;
                if (rowcnt[bm + rl] > 0 && S > 0.f) sc = rsqrtf(S);
                #pragma unroll
                for (int nt = 0; nt < 4; nt++) {
                    int col = wn * 32 + nt * 8 + lq * 2;
                    float2 bb = *(const float2*)&bias[col];
                    float2 v;
                    v.x = (d[mt][nt][2 * h + 0] + bb.x) * sc;
                    v.y = (d[mt][nt][2 * h + 1] + bb.y) * sc;
                    *(float2*)&outF[(size_t)(bm + rl) * 128 + col] = v;
                }
            }
        }
    }
}

// ============================ launch ============================
extern "C" void kernel_launch(void* const* d_in, const int* in_sizes, int n_in,
                              void* d_out, int out_size) {
    const float* ad    = (const float*)d_in[0];
    const void*  user  = d_in[1];
    const void*  ts    = d_in[2];
    const void*  click = d_in[3];
    const float* W1 = (const float*)d_in[4];
    const float* b1 = (const float*)d_in[5];
    const float* W2 = (const float*)d_in[6];
    const float* b2 = (const float*)d_in[7];
    const float* W3 = (const float*)d_in[8];
    const float* b3 = (const float*)d_in[9];
    float* out = (float*)d_out;

    cudaFuncSetAttribute(gemm_mma<128, 0>, cudaFuncAttributeMaxDynamicSharedMemorySize, GEMM_SMEM);
    cudaFuncSetAttribute(gemm_mma<512, 0>, cudaFuncAttributeMaxDynamicSharedMemorySize, GEMM_SMEM);
    cudaFuncSetAttribute(gemm_mma<256, 1>, cudaFuncAttributeMaxDynamicSharedMemorySize, GEMM_SMEM);

    __nv_bfloat16 *a0, *a1, *a2, *w1, *w2, *w3;
    int* rowcnt;
    cudaGetSymbolAddress((void**)&a0, g_a0);
    cudaGetSymbolAddress((void**)&a1, g_a1);
    cudaGetSymbolAddress((void**)&a2, g_a2);
    cudaGetSymbolAddress((void**)&w1, g_w1);
    cudaGetSymbolAddress((void**)&w2, g_w2);
    cudaGetSymbolAddress((void**)&w3, g_w3);
    cudaGetSymbolAddress((void**)&rowcnt, g_rowcnt);

    k_prep<<<1, NUSERS>>>(user, ts, click);
    k_wsplit<<<128, 256>>>(W1, W2, W3);
    k_hist<<<NROWS, DIM>>>(ad, user, ts);

    // L1: a0[8192, 2*128] @ w1[512, 2*128] -> silu -> a1 [8192, 2*512]
    gemm_mma<128, 0><<<dim3(HID1 / 128, NROWS / 128), 256, GEMM_SMEM>>>(
        a0, w1, b1, HID1, a1, nullptr, nullptr);
    // L2: a1 @ w2[256, 2*512] -> silu -> a2 [8192, 2*256]
    gemm_mma<512, 0><<<dim3(HID2 / 128, NROWS / 128), 256, GEMM_SMEM>>>(
        a1, w2, b2, HID2, a2, nullptr, nullptr);
    // L3: a2 @ w3[128, 2*256] -> bias -> L2norm -> mask -> out
    gemm_mma<256, 1><<<dim3(1, NROWS / 128), 256, GEMM_SMEM>>>(
        a2, w3, b3, DIM, nullptr, rowcnt, out);
}

// round 8
// speedup vs baseline: 1.0907x; 1.0637x over previous
#include <cuda_runtime.h>
#include <cuda_bf16.h>
#include <cstdint>
#include <math.h>

#define NROWS 8192
#define DIM   128
#define HID1  512
#define HID2  256
#define NUSERS 512

// ============ scratch: A/W stored as [hi slab | lo slab], width = 2*K ============
__device__ __align__(256) __nv_bfloat16 g_a0[NROWS * DIM * 2];    // [8192, 256]
__device__ __align__(256) __nv_bfloat16 g_a1[NROWS * HID1 * 2];   // [8192, 1024]
__device__ __align__(256) __nv_bfloat16 g_a2[NROWS * HID2 * 2];   // [8192, 512]
__device__ __align__(256) __nv_bfloat16 g_w1[HID1 * DIM * 2];     // [512, 256]   (W1^T)
__device__ __align__(256) __nv_bfloat16 g_w2[HID2 * HID1 * 2];    // [256, 1024]  (W2^T)
__device__ __align__(256) __nv_bfloat16 g_w3[DIM * HID2 * 2];     // [128, 512]   (W3^T)
__device__ int g_cnt[NUSERS], g_off[NUSERS];
__device__ int g_idx[NROWS], g_tsb[NROWS];
__device__ int g_rowcnt[NROWS];
__device__ int g_is64, g_clickbyte;

// ============================ helpers ============================
__device__ __forceinline__ uint32_t smem_to_u32(const void* p) {
    uint32_t a;
    asm("{ .reg .u64 t; cvta.to.shared.u64 t, %1; cvt.u32.u64 %0, t; }" : "=r"(a) : "l"(p));
    return a;
}
__device__ __forceinline__ void cp_async16(uint32_t smem, const void* gmem) {
    asm volatile("cp.async.cg.shared.global [%0], [%1], 16;" :: "r"(smem), "l"(gmem));
}
#define CP_COMMIT() asm volatile("cp.async.commit_group;" ::: "memory")
#define CP_WAIT(n)  asm volatile("cp.async.wait_group %0;" :: "n"(n) : "memory")

__device__ __forceinline__ void ldsm_x4(uint32_t r[4], uint32_t addr) {
    asm volatile("ldmatrix.sync.aligned.m8n8.x4.shared.b16 {%0,%1,%2,%3}, [%4];"
                 : "=r"(r[0]), "=r"(r[1]), "=r"(r[2]), "=r"(r[3]) : "r"(addr));
}
__device__ __forceinline__ void mma_bf16(float d[4], const uint32_t a[4], const uint32_t b[2]) {
    asm volatile(
        "mma.sync.aligned.m16n8k16.row.col.f32.bf16.bf16.f32 "
        "{%0,%1,%2,%3}, {%4,%5,%6,%7}, {%8,%9}, {%0,%1,%2,%3};"
        : "+f"(d[0]), "+f"(d[1]), "+f"(d[2]), "+f"(d[3])
        : "r"(a[0]), "r"(a[1]), "r"(a[2]), "r"(a[3]), "r"(b[0]), "r"(b[1]));
}
__device__ __forceinline__ void hilo_split(float v, __nv_bfloat16& hi, __nv_bfloat16& lo) {
    hi = __float2bfloat16(v);
    lo = __float2bfloat16(v - __bfloat162float(hi));
}
__device__ __forceinline__ int ld_user(const void* p, int j, int is64) {
    return is64 ? (int)((const long long*)p)[j] : ((const int*)p)[j];
}
__device__ __forceinline__ long long ld_ts(const void* p, int j, int is64) {
    return is64 ? ((const long long*)p)[j] : (long long)((const int*)p)[j];
}
__device__ __forceinline__ int ld_click(const void* p, int j, int cb) {
    return cb ? (((const unsigned char*)p)[j] != 0) : (((const int*)p)[j] != 0);
}

// ============ fused prep: detect + count + scan + scatter + sort (1 block) ============
__global__ void k_prep(const void* __restrict__ user, const void* __restrict__ ts,
                       const void* __restrict__ click) {
    __shared__ int cnt[NUSERS], off[NUSERS], fill[NUSERS];
    __shared__ int s_ts_or, s_click_big;
    int t = threadIdx.x;
    if (t == 0) { s_ts_or = 0; s_click_big = 0; }
    __syncthreads();
    {
        const unsigned int* tsw = (const unsigned int*)ts;
        unsigned int acc = 0;
        for (int i = t; i < 2048; i += NUSERS) acc |= tsw[2 * i + 1];
        if (acc) atomicOr(&s_ts_or, 1);
        const unsigned int* cw = (const unsigned int*)click;
        int big = 0;
        for (int i = t; i < 2048; i += NUSERS) if (cw[i] > 1u) big = 1;
        if (big) atomicOr(&s_click_big, 1);
    }
    cnt[t] = 0; fill[t] = 0;
    __syncthreads();
    int is64 = (s_ts_or == 0) ? 1 : 0;
    int cb = s_click_big ? 1 : 0;
    for (int j = t; j < NROWS; j += NUSERS)
        if (ld_click(click, j, cb)) atomicAdd(&cnt[ld_user(user, j, is64)], 1);
    __syncthreads();
    {
        int v = cnt[t];
        off[t] = v;
        __syncthreads();
        for (int o = 1; o < NUSERS; o <<= 1) {
            int x = (t >= o) ? off[t - o] : 0;
            __syncthreads();
            off[t] += x;
            __syncthreads();
        }
        off[t] -= v;
    }
    __syncthreads();
    for (int j = t; j < NROWS; j += NUSERS)
        if (ld_click(click, j, cb)) {
            int u = ld_user(user, j, is64);
            int pos = off[u] + atomicAdd(&fill[u], 1);
            g_idx[pos] = j;
            g_tsb[pos] = (int)ld_ts(ts, j, is64);
        }
    __syncthreads();
    {
        int b = off[t], n = cnt[t];
        for (int i = 1; i < n; i++) {
            int kj = g_idx[b + i], kt = g_tsb[b + i];
            int p = i - 1;
            while (p >= 0 && g_idx[b + p] > kj) {
                g_idx[b + p + 1] = g_idx[b + p];
                g_tsb[b + p + 1] = g_tsb[b + p];
                p--;
            }
            g_idx[b + p + 1] = kj;
            g_tsb[b + p + 1] = kt;
        }
    }
    g_off[t] = off[t];
    g_cnt[t] = cnt[t];
    if (t == 0) { g_is64 = is64; g_clickbyte = cb; }
}

// ============ history: mean of clicked-earlier ad rows -> hi/lo slabs ============
__global__ void k_hist(const float* __restrict__ ad, const void* __restrict__ user,
                       const void* __restrict__ ts) {
    int i = blockIdx.x;
    int t = threadIdx.x;           // 0..127 dim
    int is64 = g_is64;
    int u = ld_user(user, i, is64);
    long long ti = ld_ts(ts, i, is64);
    int b = g_off[u], n = g_cnt[u];
    float acc = 0.f;
    int c = 0;
    for (int k = 0; k < n; k++) {
        if ((long long)g_tsb[b + k] < ti) {
            acc += ad[g_idx[b + k] * DIM + t];
            c++;
        }
    }
    float v = c ? acc / (float)c : 0.f;
    __nv_bfloat16 hi, lo;
    hilo_split(v, hi, lo);
    g_a0[i * (2 * DIM) + t] = hi;
    g_a0[i * (2 * DIM) + DIM + t] = lo;
    if (t == 0) g_rowcnt[i] = c;
}

// ============ weight transpose + hi/lo slab split ============
__global__ void k_wsplit(const float* __restrict__ W1, const float* __restrict__ W2,
                         const float* __restrict__ W3) {
    int stride = gridDim.x * blockDim.x;
    int tid = blockIdx.x * blockDim.x + threadIdx.x;
    for (int i = tid; i < DIM * HID1; i += stride) {       // W1 [128,512] -> g_w1 [512, 2*128]
        int k = i >> 9, n = i & 511;
        __nv_bfloat16 hi, lo;
        hilo_split(W1[i], hi, lo);
        g_w1[n * (2 * DIM) + k] = hi;
        g_w1[n * (2 * DIM) + DIM + k] = lo;
    }
    for (int i = tid; i < HID1 * HID2; i += stride) {      // W2 [512,256] -> g_w2 [256, 2*512]
        int k = i >> 8, n = i & 255;
        __nv_bfloat16 hi, lo;
        hilo_split(W2[i], hi, lo);
        g_w2[n * (2 * HID1) + k] = hi;
        g_w2[n * (2 * HID1) + HID1 + k] = lo;
    }
    for (int i = tid; i < HID2 * DIM; i += stride) {       // W3 [256,128] -> g_w3 [128, 2*256]
        int k = i >> 7, n = i & 127;
        __nv_bfloat16 hi, lo;
        hilo_split(W3[i], hi, lo);
        g_w3[n * (2 * HID2) + k] = hi;
        g_w3[n * (2 * HID2) + HID2 + k] = lo;
    }
}

// ============ mma.sync GEMM: BMx128 CTA tile, virtual K' = 3*KLOG via 3 segments ============
// A: [M, 2*KLOG] = [Ahi | Alo], B: [Nfull, 2*KLOG] = [Bhi | Blo] (= W^T split).
// Segment s: s=0 -> Ahi*Bhi, s=1 -> Ahi*Blo, s=2 -> Alo*Bhi
//   => D = AhiBhi + AhiBlo + AloBhi  (3-term compensated bf16).
// K-chunk 64, 3-stage cp.async pipeline, ldmatrix fragment loads, 144B-padded rows.
// EPI 0: bias+SiLU -> hi/lo slab bf16 out. EPI 1: bias -> L2 norm -> mask -> fp32 out.
#define ROWB 144
#define BMATB (128 * ROWB)     // B tile bytes (BN always 128)

template<int KLOG, int EPI, int BM>
__global__ __launch_bounds__(256, 2)
void gemm_mma(const __nv_bfloat16* __restrict__ A, const __nv_bfloat16* __restrict__ B,
              const float* __restrict__ bias, int Nfull,
              __nv_bfloat16* __restrict__ outAB,
              const int* __restrict__ rowcnt, float* __restrict__ outF) {
    constexpr int KT = 2 * KLOG;
    constexpr int CPS = KLOG / 64;
    constexpr int NCH = 3 * CPS;
    constexpr int MT = BM / 32;               // m-tiles per warp (warp m-span = MT*16)
    constexpr int AMATB = BM * ROWB;
    constexpr int STG = AMATB + BMATB;        // bytes per pipeline stage
    extern __shared__ char sm[];
    const int tid = threadIdx.x, wid = tid >> 5, lane = tid & 31;
    const int wm = wid & 1, wn = wid >> 1;    // 2 (m) x 4 (n) warps
    const int lq = lane & 3, lr = lane >> 2;
    const int bm = blockIdx.y * BM, bn = blockIdx.x * 128;
    const uint32_t smem0 = smem_to_u32(sm);

    const uint32_t aOff = (uint32_t)((((lane >> 3) & 1) * 8 + (lane & 7)) * ROWB
                                     + (lane >> 4) * 16 + (wm * MT * 16) * ROWB);
    const uint32_t bOff = (uint32_t)(((((lane >> 4) & 1) * 8) + (lane & 7)) * ROWB
                                     + ((lane >> 3) & 1) * 16 + (wn * 32) * ROWB);

    float d[MT][4][4];
    #pragma unroll
    for (int mt = 0; mt < MT; mt++)
        #pragma unroll
        for (int nt = 0; nt < 4; nt++)
            #pragma unroll
            for (int q = 0; q < 4; q++) d[mt][nt][q] = 0.f;

    auto load_stage = [&](int s, int ch) {
        int seg = ch / CPS;
        int ks0 = (ch - seg * CPS) * 64;
        int aO = (seg == 2) ? (KLOG + ks0) : ks0;     // seg 0,1: Ahi; seg 2: Alo
        int bO = (seg == 1) ? (KLOG + ks0) : ks0;     // seg 0,2: Bhi; seg 1: Blo
        uint32_t sb = smem0 + (uint32_t)s * STG;
        #pragma unroll
        for (int i = tid; i < BM * 8; i += 256) {
            int r = i >> 3, c = i & 7;
            cp_async16(sb + (uint32_t)(r * ROWB + c * 16),
                       A + (size_t)(bm + r) * KT + aO + c * 8);
        }
        #pragma unroll
        for (int i = tid; i < 1024; i += 256) {
            int r = i >> 3, c = i & 7;
            cp_async16(sb + AMATB + (uint32_t)(r * ROWB + c * 16),
                       B + (size_t)(bn + r) * KT + bO + c * 8);
        }
    };

    load_stage(0, 0);
    CP_COMMIT();
    load_stage(1, 1);
    CP_COMMIT();

    int stage = 0;
    for (int ch = 0; ch < NCH; ch++) {
        if (ch + 1 < NCH) { CP_WAIT(1); } else { CP_WAIT(0); }
        __syncthreads();
        if (ch + 2 < NCH) {
            int ns = stage + 2; if (ns >= 3) ns -= 3;
            load_stage(ns, ch + 2);
            CP_COMMIT();
        }
        uint32_t sA = smem0 + (uint32_t)stage * STG;
        uint32_t sB = sA + AMATB;
        #pragma unroll
        for (int ks = 0; ks < 4; ks++) {
            uint32_t Af[MT][4], Bf[2][4];
            #pragma unroll
            for (int mt = 0; mt < MT; mt++)
                ldsm_x4(Af[mt], sA + aOff + (uint32_t)(mt * 16 * ROWB + ks * 32));
            ldsm_x4(Bf[0], sB + bOff + (uint32_t)(ks * 32));
            ldsm_x4(Bf[1], sB + bOff + (uint32_t)(16 * ROWB + ks * 32));
            #pragma unroll
            for (int mt = 0; mt < MT; mt++)
                #pragma unroll
                for (int nt = 0; nt < 4; nt++)
                    mma_bf16(d[mt][nt], Af[mt], &Bf[nt >> 1][(nt & 1) * 2]);
        }
        stage++; if (stage >= 3) stage = 0;
    }
    __syncthreads();

    if (EPI == 0) {
        // bias + SiLU -> hi/lo slab store (out width = 2*Nfull)
        #pragma unroll
        for (int mt = 0; mt < MT; mt++) {
            int row0 = bm + wm * MT * 16 + mt * 16 + lr;
            #pragma unroll
            for (int nt = 0; nt < 4; nt++) {
                int col = bn + wn * 32 + nt * 8 + lq * 2;
                float2 bb = *(const float2*)&bias[col];
                #pragma unroll
                for (int h = 0; h < 2; h++) {
                    int row = row0 + h * 8;
                    float x0 = d[mt][nt][2 * h + 0] + bb.x;
                    float x1 = d[mt][nt][2 * h + 1] + bb.y;
                    float s0 = x0 / (1.f + __expf(-x0));
                    float s1 = x1 / (1.f + __expf(-x1));
                    __nv_bfloat16 h0, l0, h1, l1;
                    hilo_split(s0, h0, l0);
                    hilo_split(s1, h1, l1);
                    __nv_bfloat162 ph = __halves2bfloat162(h0, h1);
                    __nv_bfloat162 pl = __halves2bfloat162(l0, l1);
                    size_t rbase = (size_t)row * (2 * Nfull);
                    ((uint32_t*)outAB)[(rbase + col) >> 1]         = *(uint32_t*)&ph;
                    ((uint32_t*)outAB)[(rbase + Nfull + col) >> 1] = *(uint32_t*)&pl;
                }
            }
        }
    } else {
        // bias + L2 norm + empty mask (Nfull == 128, bn == 0); deterministic reduce
        float* sqp = (float*)sm;   // [4 n-warps][BM rows]
        for (int i = tid; i < 4 * BM; i += 256) sqp[i] = 0.f;
        __syncthreads();
        #pragma unroll
        for (int mt = 0; mt < MT; mt++) {
            #pragma unroll
            for (int h = 0; h < 2; h++) {
                float s = 0.f;
                #pragma unroll
                for (int nt = 0; nt < 4; nt++) {
                    int col = wn * 32 + nt * 8 + lq * 2;
                    float2 bb = *(const float2*)&bias[col];
                    float e0 = d[mt][nt][2 * h + 0] + bb.x;
                    float e1 = d[mt][nt][2 * h + 1] + bb.y;
                    s += e0 * e0 + e1 * e1;
                }
                s += __shfl_xor_sync(0xffffffffu, s, 1);
                s += __shfl_xor_sync(0xffffffffu, s, 2);
                if (lq == 0) sqp[wn * BM + wm * MT * 16 + mt * 16 + lr + h * 8] = s;
            }
        }
        __syncthreads();
        #pragma unroll
        for (int mt = 0; mt < MT; mt++) {
            #pragma unroll
            for (int h = 0; h < 2; h++) {
                int rl = wm * MT * 16 + mt * 16 + lr + h * 8;
                float S = sqp[rl] + sqp[BM + rl] + sqp[2 * BM + rl] + sqp[3 * BM + rl];
                float sc = 0.f;
                if (rowcnt[bm + rl] > 0 && S > 0.f) sc = rsqrtf(S);
                #pragma unroll
                for (int nt = 0; nt < 4; nt++) {
                    int col = wn * 32 + nt * 8 + lq * 2;
                    float2 bb = *(const float2*)&bias[col];
                    float2 v;
                    v.x = (d[mt][nt][2 * h + 0] + bb.x) * sc;
                    v.y = (d[mt][nt][2 * h + 1] + bb.y) * sc;
                    *(float2*)&outF[(size_t)(bm + rl) * 128 + col] = v;
                }
            }
        }
    }
}

// ============================ launch ============================
extern "C" void kernel_launch(void* const* d_in, const int* in_sizes, int n_in,
                              void* d_out, int out_size) {
    const float* ad    = (const float*)d_in[0];
    const void*  user  = d_in[1];
    const void*  ts    = d_in[2];
    const void*  click = d_in[3];
    const float* W1 = (const float*)d_in[4];
    const float* b1 = (const float*)d_in[5];
    const float* W2 = (const float*)d_in[6];
    const float* b2 = (const float*)d_in[7];
    const float* W3 = (const float*)d_in[8];
    const float* b3 = (const float*)d_in[9];
    float* out = (float*)d_out;

    constexpr int SMEM_L1 = 3 * (128 * ROWB + BMATB);   // 110592
    constexpr int SMEM_S  = 3 * (64 * ROWB + BMATB);    // 82944
    cudaFuncSetAttribute(gemm_mma<128, 0, 128>, cudaFuncAttributeMaxDynamicSharedMemorySize, SMEM_L1);
    cudaFuncSetAttribute(gemm_mma<512, 0, 64>,  cudaFuncAttributeMaxDynamicSharedMemorySize, SMEM_S);
    cudaFuncSetAttribute(gemm_mma<256, 1, 64>,  cudaFuncAttributeMaxDynamicSharedMemorySize, SMEM_S);

    __nv_bfloat16 *a0, *a1, *a2, *w1, *w2, *w3;
    int* rowcnt;
    cudaGetSymbolAddress((void**)&a0, g_a0);
    cudaGetSymbolAddress((void**)&a1, g_a1);
    cudaGetSymbolAddress((void**)&a2, g_a2);
    cudaGetSymbolAddress((void**)&w1, g_w1);
    cudaGetSymbolAddress((void**)&w2, g_w2);
    cudaGetSymbolAddress((void**)&w3, g_w3);
    cudaGetSymbolAddress((void**)&rowcnt, g_rowcnt);

    k_prep<<<1, NUSERS>>>(user, ts, click);
    k_wsplit<<<128, 256>>>(W1, W2, W3);
    k_hist<<<NROWS, DIM>>>(ad, user, ts);

    // L1: a0[8192, 2*128] @ w1[512, 2*128] -> silu -> a1 [8192, 2*512]   grid 256
    gemm_mma<128, 0, 128><<<dim3(HID1 / 128, NROWS / 128), 256, SMEM_L1>>>(
        a0, w1, b1, HID1, a1, nullptr, nullptr);
    // L2: a1 @ w2[256, 2*512] -> silu -> a2 [8192, 2*256]                grid 256
    gemm_mma<512, 0, 64><<<dim3(HID2 / 128, NROWS / 64), 256, SMEM_S>>>(
        a1, w2, b2, HID2, a2, nullptr, nullptr);
    // L3: a2 @ w3[128, 2*256] -> bias -> L2norm -> mask -> out           grid 128
    gemm_mma<256, 1, 64><<<dim3(1, NROWS / 64), 256, SMEM_S>>>(
        a2, w3, b3, DIM, nullptr, rowcnt, out);
}

// round 9
// speedup vs baseline: 1.6538x; 1.5163x over previous
#include <cuda_runtime.h>
#include <cuda_fp16.h>
#include <cstdint>
#include <math.h>

#define NROWS 8192
#define DIM   128
#define HID1  512
#define HID2  256
#define NUSERS 512

// ============ scratch: plain fp16 activations + transposed fp16 weights ============
__device__ __align__(256) __half g_a0[NROWS * DIM];     // [8192, 128]
__device__ __align__(256) __half g_a1[NROWS * HID1];    // [8192, 512]
__device__ __align__(256) __half g_a2[NROWS * HID2];    // [8192, 256]
__device__ __align__(256) __half g_w1[HID1 * DIM];      // [512, 128]  (W1^T)
__device__ __align__(256) __half g_w2[HID2 * HID1];     // [256, 512]  (W2^T)
__device__ __align__(256) __half g_w3[DIM * HID2];      // [128, 256]  (W3^T)
__device__ int g_cnt[NUSERS], g_off[NUSERS];
__device__ int g_idx[NROWS], g_tsb[NROWS];
__device__ int g_rowcnt[NROWS];
__device__ int g_is64, g_clickbyte;

// ============================ helpers ============================
__device__ __forceinline__ uint32_t smem_to_u32(const void* p) {
    uint32_t a;
    asm("{ .reg .u64 t; cvta.to.shared.u64 t, %1; cvt.u32.u64 %0, t; }" : "=r"(a) : "l"(p));
    return a;
}
__device__ __forceinline__ void cp_async16(uint32_t smem, const void* gmem) {
    asm volatile("cp.async.cg.shared.global [%0], [%1], 16;" :: "r"(smem), "l"(gmem));
}
#define CP_COMMIT() asm volatile("cp.async.commit_group;" ::: "memory")
#define CP_WAIT(n)  asm volatile("cp.async.wait_group %0;" :: "n"(n) : "memory")

__device__ __forceinline__ void ldsm_x4(uint32_t r[4], uint32_t addr) {
    asm volatile("ldmatrix.sync.aligned.m8n8.x4.shared.b16 {%0,%1,%2,%3}, [%4];"
                 : "=r"(r[0]), "=r"(r[1]), "=r"(r[2]), "=r"(r[3]) : "r"(addr));
}
__device__ __forceinline__ void mma_fp16(float d[4], const uint32_t a[4], const uint32_t b[2]) {
    asm volatile(
        "mma.sync.aligned.m16n8k16.row.col.f32.f16.f16.f32 "
        "{%0,%1,%2,%3}, {%4,%5,%6,%7}, {%8,%9}, {%0,%1,%2,%3};"
        : "+f"(d[0]), "+f"(d[1]), "+f"(d[2]), "+f"(d[3])
        : "r"(a[0]), "r"(a[1]), "r"(a[2]), "r"(a[3]), "r"(b[0]), "r"(b[1]));
}
__device__ __forceinline__ int ld_user(const void* p, int j, int is64) {
    return is64 ? (int)((const long long*)p)[j] : ((const int*)p)[j];
}
__device__ __forceinline__ long long ld_ts(const void* p, int j, int is64) {
    return is64 ? ((const long long*)p)[j] : (long long)((const int*)p)[j];
}
__device__ __forceinline__ int ld_click(const void* p, int j, int cb) {
    return cb ? (((const unsigned char*)p)[j] != 0) : (((const int*)p)[j] != 0);
}

// ============ fused prep: detect + count + scan + scatter + sort (1 block) ============
__global__ void k_prep(const void* __restrict__ user, const void* __restrict__ ts,
                       const void* __restrict__ click) {
    __shared__ int cnt[NUSERS], off[NUSERS], fill[NUSERS];
    __shared__ int s_ts_or, s_click_big;
    int t = threadIdx.x;
    if (t == 0) { s_ts_or = 0; s_click_big = 0; }
    __syncthreads();
    {
        const unsigned int* tsw = (const unsigned int*)ts;
        unsigned int acc = 0;
        for (int i = t; i < 2048; i += NUSERS) acc |= tsw[2 * i + 1];
        if (acc) atomicOr(&s_ts_or, 1);
        const unsigned int* cw = (const unsigned int*)click;
        int big = 0;
        for (int i = t; i < 2048; i += NUSERS) if (cw[i] > 1u) big = 1;
        if (big) atomicOr(&s_click_big, 1);
    }
    cnt[t] = 0; fill[t] = 0;
    __syncthreads();
    int is64 = (s_ts_or == 0) ? 1 : 0;
    int cb = s_click_big ? 1 : 0;
    for (int j = t; j < NROWS; j += NUSERS)
        if (ld_click(click, j, cb)) atomicAdd(&cnt[ld_user(user, j, is64)], 1);
    __syncthreads();
    {
        int v = cnt[t];
        off[t] = v;
        __syncthreads();
        for (int o = 1; o < NUSERS; o <<= 1) {
            int x = (t >= o) ? off[t - o] : 0;
            __syncthreads();
            off[t] += x;
            __syncthreads();
        }
        off[t] -= v;
    }
    __syncthreads();
    for (int j = t; j < NROWS; j += NUSERS)
        if (ld_click(click, j, cb)) {
            int u = ld_user(user, j, is64);
            int pos = off[u] + atomicAdd(&fill[u], 1);
            g_idx[pos] = j;
            g_tsb[pos] = (int)ld_ts(ts, j, is64);
        }
    __syncthreads();
    {
        int b = off[t], n = cnt[t];
        for (int i = 1; i < n; i++) {
            int kj = g_idx[b + i], kt = g_tsb[b + i];
            int p = i - 1;
            while (p >= 0 && g_idx[b + p] > kj) {
                g_idx[b + p + 1] = g_idx[b + p];
                g_tsb[b + p + 1] = g_tsb[b + p];
                p--;
            }
            g_idx[b + p + 1] = kj;
            g_tsb[b + p + 1] = kt;
        }
    }
    g_off[t] = off[t];
    g_cnt[t] = cnt[t];
    if (t == 0) { g_is64 = is64; g_clickbyte = cb; }
}

// ============ history: mean of clicked-earlier ad rows -> fp16 ============
__global__ void k_hist(const float* __restrict__ ad, const void* __restrict__ user,
                       const void* __restrict__ ts) {
    int i = blockIdx.x;
    int t = threadIdx.x;           // 0..127 dim
    int is64 = g_is64;
    int u = ld_user(user, i, is64);
    long long ti = ld_ts(ts, i, is64);
    int b = g_off[u], n = g_cnt[u];
    float acc = 0.f;
    int c = 0;
    for (int k = 0; k < n; k++) {
        if ((long long)g_tsb[b + k] < ti) {
            acc += ad[g_idx[b + k] * DIM + t];
            c++;
        }
    }
    float v = c ? acc / (float)c : 0.f;
    g_a0[i * DIM + t] = __float2half(v);
    if (t == 0) g_rowcnt[i] = c;
}

// ============ weight transpose -> fp16 ============
__global__ void k_wt(const float* __restrict__ W1, const float* __restrict__ W2,
                     const float* __restrict__ W3) {
    int stride = gridDim.x * blockDim.x;
    int tid = blockIdx.x * blockDim.x + threadIdx.x;
    for (int i = tid; i < DIM * HID1; i += stride) {       // W1 [128,512] -> g_w1 [512,128]
        int k = i >> 9, n = i & 511;
        g_w1[n * DIM + k] = __float2half(W1[i]);
    }
    for (int i = tid; i < HID1 * HID2; i += stride) {      // W2 [512,256] -> g_w2 [256,512]
        int k = i >> 8, n = i & 255;
        g_w2[n * HID1 + k] = __float2half(W2[i]);
    }
    for (int i = tid; i < HID2 * DIM; i += stride) {       // W3 [256,128] -> g_w3 [128,256]
        int k = i >> 7, n = i & 127;
        g_w3[n * HID2 + k] = __float2half(W3[i]);
    }
}

// ============ mma.sync fp16 GEMM: BMx128 CTA tile ============
// A: [M,K] row-major fp16, B: [Nfull,K] row-major fp16 (= W^T). fp32 accum.
// K-chunk 64, up-to-3-stage cp.async pipeline, ldmatrix frags, 144B-padded rows.
// EPI 0: bias+SiLU -> fp16 out. EPI 1: bias -> L2 norm -> empty mask -> fp32 out.
#define ROWB 144
#define BMATB (128 * ROWB)     // B tile bytes (BN always 128)

template<int K, int EPI, int BM>
__global__ __launch_bounds__(256, 2)
void gemm_mma(const __half* __restrict__ A, const __half* __restrict__ B,
              const float* __restrict__ bias, int Nfull,
              __half* __restrict__ outH,
              const int* __restrict__ rowcnt, float* __restrict__ outF) {
    constexpr int NCH = K / 64;
    constexpr int NSTG = (NCH < 3) ? NCH : 3;
    constexpr int MT = BM / 32;               // m-tiles per warp
    constexpr int AMATB = BM * ROWB;
    constexpr int STG = AMATB + BMATB;
    extern __shared__ char sm[];
    const int tid = threadIdx.x, wid = tid >> 5, lane = tid & 31;
    const int wm = wid & 1, wn = wid >> 1;    // 2 (m) x 4 (n) warps
    const int lq = lane & 3, lr = lane >> 2;
    const int bm = blockIdx.y * BM, bn = blockIdx.x * 128;
    const uint32_t smem0 = smem_to_u32(sm);

    const uint32_t aOff = (uint32_t)((((lane >> 3) & 1) * 8 + (lane & 7)) * ROWB
                                     + (lane >> 4) * 16 + (wm * MT * 16) * ROWB);
    const uint32_t bOff = (uint32_t)(((((lane >> 4) & 1) * 8) + (lane & 7)) * ROWB
                                     + ((lane >> 3) & 1) * 16 + (wn * 32) * ROWB);

    float d[MT][4][4];
    #pragma unroll
    for (int mt = 0; mt < MT; mt++)
        #pragma unroll
        for (int nt = 0; nt < 4; nt++)
            #pragma unroll
            for (int q = 0; q < 4; q++) d[mt][nt][q] = 0.f;

    auto load_stage = [&](int s, int ch) {
        int k0 = ch * 64;
        uint32_t sb = smem0 + (uint32_t)s * STG;
        #pragma unroll
        for (int i = tid; i < BM * 8; i += 256) {
            int r = i >> 3, c = i & 7;
            cp_async16(sb + (uint32_t)(r * ROWB + c * 16),
                       A + (size_t)(bm + r) * K + k0 + c * 8);
        }
        #pragma unroll
        for (int i = tid; i < 1024; i += 256) {
            int r = i >> 3, c = i & 7;
            cp_async16(sb + AMATB + (uint32_t)(r * ROWB + c * 16),
                       B + (size_t)(bn + r) * K + k0 + c * 8);
        }
    };

    load_stage(0, 0);
    CP_COMMIT();
    if (NCH > 1) { load_stage(1, 1); CP_COMMIT(); }

    int stage = 0;
    for (int ch = 0; ch < NCH; ch++) {
        if (ch + 1 < NCH) { CP_WAIT(1); } else { CP_WAIT(0); }
        __syncthreads();
        if (ch + 2 < NCH) {
            int ns = stage + 2; if (ns >= NSTG) ns -= NSTG;
            load_stage(ns, ch + 2);
            CP_COMMIT();
        }
        uint32_t sA = smem0 + (uint32_t)stage * STG;
        uint32_t sB = sA + AMATB;
        #pragma unroll
        for (int ks = 0; ks < 4; ks++) {
            uint32_t Af[MT][4], Bf[2][4];
            #pragma unroll
            for (int mt = 0; mt < MT; mt++)
                ldsm_x4(Af[mt], sA + aOff + (uint32_t)(mt * 16 * ROWB + ks * 32));
            ldsm_x4(Bf[0], sB + bOff + (uint32_t)(ks * 32));
            ldsm_x4(Bf[1], sB + bOff + (uint32_t)(16 * ROWB + ks * 32));
            #pragma unroll
            for (int mt = 0; mt < MT; mt++)
                #pragma unroll
                for (int nt = 0; nt < 4; nt++)
                    mma_fp16(d[mt][nt], Af[mt], &Bf[nt >> 1][(nt & 1) * 2]);
        }
        stage++; if (stage >= NSTG) stage = 0;
    }
    __syncthreads();

    if (EPI == 0) {
        // bias + SiLU -> fp16 store
        #pragma unroll
        for (int mt = 0; mt < MT; mt++) {
            int row0 = bm + wm * MT * 16 + mt * 16 + lr;
            #pragma unroll
            for (int nt = 0; nt < 4; nt++) {
                int col = bn + wn * 32 + nt * 8 + lq * 2;
                float2 bb = *(const float2*)&bias[col];
                #pragma unroll
                for (int h = 0; h < 2; h++) {
                    int row = row0 + h * 8;
                    float x0 = d[mt][nt][2 * h + 0] + bb.x;
                    float x1 = d[mt][nt][2 * h + 1] + bb.y;
                    float s0 = x0 / (1.f + __expf(-x0));
                    float s1 = x1 / (1.f + __expf(-x1));
                    __half2 p = __floats2half2_rn(s0, s1);
                    ((uint32_t*)outH)[((size_t)row * Nfull + col) >> 1] = *(uint32_t*)&p;
                }
            }
        }
    } else {
        // bias + L2 norm + empty mask (Nfull == 128, bn == 0); deterministic reduce
        float* sqp = (float*)sm;   // [4 n-warps][BM rows]
        for (int i = tid; i < 4 * BM; i += 256) sqp[i] = 0.f;
        __syncthreads();
        #pragma unroll
        for (int mt = 0; mt < MT; mt++) {
            #pragma unroll
            for (int h = 0; h < 2; h++) {
                float s = 0.f;
                #pragma unroll
                for (int nt = 0; nt < 4; nt++) {
                    int col = wn * 32 + nt * 8 + lq * 2;
                    float2 bb = *(const float2*)&bias[col];
                    float e0 = d[mt][nt][2 * h + 0] + bb.x;
                    float e1 = d[mt][nt][2 * h + 1] + bb.y;
                    s += e0 * e0 + e1 * e1;
                }
                s += __shfl_xor_sync(0xffffffffu, s, 1);
                s += __shfl_xor_sync(0xffffffffu, s, 2);
                if (lq == 0) sqp[wn * BM + wm * MT * 16 + mt * 16 + lr + h * 8] = s;
            }
        }
        __syncthreads();
        #pragma unroll
        for (int mt = 0; mt < MT; mt++) {
            #pragma unroll
            for (int h = 0; h < 2; h++) {
                int rl = wm * MT * 16 + mt * 16 + lr + h * 8;
                float S = sqp[rl] + sqp[BM + rl] + sqp[2 * BM + rl] + sqp[3 * BM + rl];
                float sc = 0.f;
                if (rowcnt[bm + rl] > 0 && S > 0.f) sc = rsqrtf(S);
                #pragma unroll
                for (int nt = 0; nt < 4; nt++) {
                    int col = wn * 32 + nt * 8 + lq * 2;
                    float2 bb = *(const float2*)&bias[col];
                    float2 v;
                    v.x = (d[mt][nt][2 * h + 0] + bb.x) * sc;
                    v.y = (d[mt][nt][2 * h + 1] + bb.y) * sc;
                    *(float2*)&outF[(size_t)(bm + rl) * 128 + col] = v;
                }
            }
        }
    }
}

// ============================ launch ============================
extern "C" void kernel_launch(void* const* d_in, const int* in_sizes, int n_in,
                              void* d_out, int out_size) {
    const float* ad    = (const float*)d_in[0];
    const void*  user  = d_in[1];
    const void*  ts    = d_in[2];
    const void*  click = d_in[3];
    const float* W1 = (const float*)d_in[4];
    const float* b1 = (const float*)d_in[5];
    const float* W2 = (const float*)d_in[6];
    const float* b2 = (const float*)d_in[7];
    const float* W3 = (const float*)d_in[8];
    const float* b3 = (const float*)d_in[9];
    float* out = (float*)d_out;

    constexpr int SMEM_L1 = 2 * (128 * ROWB + BMATB);   // 2 stages (NCH=2) = 73728
    constexpr int SMEM_L2 = 3 * (64 * ROWB + BMATB);    // 3 stages = 82944
    constexpr int SMEM_L3 = 3 * (64 * ROWB + BMATB);
    cudaFuncSetAttribute(gemm_mma<128, 0, 128>, cudaFuncAttributeMaxDynamicSharedMemorySize, SMEM_L1);
    cudaFuncSetAttribute(gemm_mma<512, 0, 64>,  cudaFuncAttributeMaxDynamicSharedMemorySize, SMEM_L2);
    cudaFuncSetAttribute(gemm_mma<256, 1, 64>,  cudaFuncAttributeMaxDynamicSharedMemorySize, SMEM_L3);

    __half *a0, *a1, *a2, *w1, *w2, *w3;
    int* rowcnt;
    cudaGetSymbolAddress((void**)&a0, g_a0);
    cudaGetSymbolAddress((void**)&a1, g_a1);
    cudaGetSymbolAddress((void**)&a2, g_a2);
    cudaGetSymbolAddress((void**)&w1, g_w1);
    cudaGetSymbolAddress((void**)&w2, g_w2);
    cudaGetSymbolAddress((void**)&w3, g_w3);
    cudaGetSymbolAddress((void**)&rowcnt, g_rowcnt);

    k_prep<<<1, NUSERS>>>(user, ts, click);
    k_wt<<<128, 256>>>(W1, W2, W3);
    k_hist<<<NROWS, DIM>>>(ad, user, ts);

    // L1: a0[8192,128] @ w1[512,128]^T -> silu -> a1 [8192,512]    grid 256
    gemm_mma<128, 0, 128><<<dim3(HID1 / 128, NROWS / 128), 256, SMEM_L1>>>(
        a0, w1, b1, HID1, a1, nullptr, nullptr);
    // L2: a1 @ w2[256,512]^T -> silu -> a2 [8192,256]              grid 256
    gemm_mma<512, 0, 64><<<dim3(HID2 / 128, NROWS / 64), 256, SMEM_L2>>>(
        a1, w2, b2, HID2, a2, nullptr, nullptr);
    // L3: a2 @ w3[128,256]^T -> bias -> L2norm -> mask -> out      grid 128
    gemm_mma<256, 1, 64><<<dim3(1, NROWS / 64), 256, SMEM_L3>>>(
        a2, w3, b3, DIM, nullptr, rowcnt, out);
}